// round 10
// baseline (speedup 1.0000x reference)
#include <cuda_runtime.h>
#include <math.h>

#define NN 8192
#define EE 131072
#define DIM 32
#define HID 128
#define BG 64
#define NMP 3
#define S2S 3
#define KDIM 4096   // HID*DIM

typedef unsigned long long ull;

__device__ __forceinline__ ull pk2(float lo, float hi) {
    ull r; asm("mov.b64 %0,{%1,%2};" : "=l"(r) : "f"(lo), "f"(hi)); return r;
}
__device__ __forceinline__ float2 upk2(ull v) {
    float2 r; asm("mov.b64 {%0,%1},%2;" : "=f"(r.x), "=f"(r.y) : "l"(v)); return r;
}
__device__ __forceinline__ ull ffma2(ull a, ull b, ull c) {
    ull d; asm("fma.rn.f32x2 %0,%1,%2,%3;" : "=l"(d) : "l"(a), "l"(b), "l"(c)); return d;
}
__device__ __forceinline__ ull add2(ull a, ull b) {
    ull d; asm("add.rn.f32x2 %0,%1,%2;" : "=l"(d) : "l"(a), "l"(b)); return d;
}

// ---------------- scratch (device globals; no allocation) ----------------
__device__ float g_out[NN * DIM];            // node features / GRU hidden
__device__ float g_V[(size_t)NN * KDIM];     // V[s][k][o]
__device__ float g_agg[NN * DIM];            // atomic message accum (re-zeroed by k_update)
__device__ int   g_cnt[NN];
__device__ int   g_dcnt[NN];
__device__ int   g_rowptr[NN + 1];
__device__ int   g_woff[NN];
__device__ int   g_eids[EE];
__device__ float g_deg[NN];
__device__ int   g_gptr[BG + 1];
__device__ float g_qh[BG * DIM];
__device__ float g_qc[BG * DIM];
__device__ float g_qstar[BG * 2 * DIM];

__device__ __forceinline__ float sigm(float x) { return 1.0f / (1.0f + expf(-x)); }

// ---------------- setup ----------------
__global__ void k_zeroinit(const float* __restrict__ x,
                           const float* __restrict__ w0,
                           const float* __restrict__ b0) {
    int idx = blockIdx.x * blockDim.x + threadIdx.x;
    if (idx < NN) { g_cnt[idx] = 0; g_dcnt[idx] = 0; }
    if (idx < NN * DIM) {
        int n = idx >> 5, j = idx & 31;
        float v = x[n] * w0[j] + b0[j];
        g_out[idx] = v > 0.f ? v : 0.f;
    }
}

// 1 edge/thread, 512 blocks: max warps in flight to hide atomic latency
__global__ void k_count(const int* __restrict__ ei) {
    int e = blockIdx.x * blockDim.x + threadIdx.x;
    if (e < EE) {
        atomicAdd(&g_cnt[ei[e]], 1);          // src (CSR grouping)
        atomicAdd(&g_dcnt[ei[EE + e]], 1);    // dst (degree for mean)
    }
}

// shfl-based exclusive scan of src counts -> rowptr/woff; deg from dcnt
__global__ void k_scan() {
    __shared__ int wsum[32], wscan[32];
    int t = threadIdx.x, lane = t & 31, wid = t >> 5;
    int base = t * 8;
    int v[8]; int csum = 0;
#pragma unroll
    for (int i = 0; i < 8; i++) { v[i] = g_cnt[base + i]; csum += v[i]; }
    int inc = csum;
#pragma unroll
    for (int off = 1; off < 32; off <<= 1) {
        int nv = __shfl_up_sync(0xffffffffu, inc, off);
        if (lane >= off) inc += nv;
    }
    if (lane == 31) wsum[wid] = inc;
    __syncthreads();
    if (t < 32) {
        int w = wsum[t];
#pragma unroll
        for (int off = 1; off < 32; off <<= 1) {
            int nv = __shfl_up_sync(0xffffffffu, w, off);
            if (t >= off) w += nv;
        }
        wscan[t] = w;
    }
    __syncthreads();
    int run = inc - csum + (wid > 0 ? wscan[wid - 1] : 0);
#pragma unroll
    for (int i = 0; i < 8; i++) {
        g_rowptr[base + i] = run;
        g_woff[base + i] = run;
        run += v[i];
    }
    if (t == 1023) g_rowptr[NN] = run;
#pragma unroll
    for (int i = 0; i < 8; i++) {
        int d = g_dcnt[base + i];
        g_deg[base + i] = (float)(d > 0 ? d : 1);
    }
}

// CSR fill, 1 edge/thread (+ per-graph ranges in block 0)
__global__ void k_fill(const int* __restrict__ ei, const int* __restrict__ batch) {
    int e = blockIdx.x * blockDim.x + threadIdx.x;
    if (e < EE) {
        int src = ei[e];
        int pos = atomicAdd(&g_woff[src], 1);
        g_eids[pos] = e;
    }
    if (blockIdx.x == 0 && threadIdx.x <= BG) {
        int b = threadIdx.x;
        int lo = 0, hi = NN;
        while (lo < hi) {
            int mid = (lo + hi) >> 1;
            if (batch[mid] < b) lo = mid + 1; else hi = mid;
        }
        g_gptr[b] = lo;
    }
}

// ---------------- V GEMM: V[N,4096] = out[N,32] @ B[32,4096] ----------------
// grid 2048 = 128 node-tiles x 16 r-chunks (256 cols each); block 256.
__global__ void k_vgemm(const float* __restrict__ w2) {
    __shared__ ull  At2[64][32];    // [n][d] pk2(a,a)   16KB
    __shared__ float Bs[32][256];   // [d][rr]           32KB
    int tid = threadIdx.x;
    int ntile = blockIdx.x & 127;
    int rchunk = blockIdx.x >> 7;
    int rbase = rchunk * 256;
    int nodebase = ntile * 64;

#pragma unroll
    for (int i = 0; i < 8; i++) {
        int s = i * 256 + tid;
        int n = s >> 5, d = s & 31;
        float a = g_out[(nodebase + n) * DIM + d];
        At2[n][d] = pk2(a, a);
    }
#pragma unroll
    for (int i = 0; i < 8; i++) {
        int s = i * 256 + tid;
        int d = s >> 6, rq = s & 63;
        int r = rbase + rq * 4;
        int k = r >> 5, o = r & 31;
        *(float4*)&Bs[d][rq * 4] = *(const float4*)&w2[(size_t)k * 1024 + d * 32 + o];
    }
    __syncthreads();

    int w = tid >> 5, l = tid & 31;
    ull acc[8][4];
#pragma unroll
    for (int j = 0; j < 8; j++)
#pragma unroll
        for (int q = 0; q < 4; q++) acc[j][q] = 0ull;

#pragma unroll 4
    for (int d = 0; d < 32; d++) {
        ull b0 = *(const ull*)&Bs[d][2 * l];
        ull b1 = *(const ull*)&Bs[d][64 + 2 * l];
        ull b2 = *(const ull*)&Bs[d][128 + 2 * l];
        ull b3 = *(const ull*)&Bs[d][192 + 2 * l];
#pragma unroll
        for (int j = 0; j < 8; j++) {
            ull a = At2[w + 8 * j][d];
            acc[j][0] = ffma2(a, b0, acc[j][0]);
            acc[j][1] = ffma2(a, b1, acc[j][1]);
            acc[j][2] = ffma2(a, b2, acc[j][2]);
            acc[j][3] = ffma2(a, b3, acc[j][3]);
        }
    }
#pragma unroll
    for (int j = 0; j < 8; j++) {
        int n = nodebase + w + 8 * j;
        float* Vr = g_V + (size_t)n * KDIM + rbase;
#pragma unroll
        for (int q = 0; q < 4; q++) {
            float2 v = upk2(acc[j][q]);
            *(float2*)&Vr[64 * q + 2 * l] = v;
        }
    }
}

// ---------------- edge contraction + scatter (per src node) ----------------
// 16 edges (8 f32x2 pairs) per batch. h staged as sh2[k][pair] so the inner
// loop is 4x LDS.128 (8 h-packs) + 8 FFMA2 per kk (issue ratio 1.5).
__global__ void k_edges(const int* __restrict__ ei, const float* __restrict__ ea,
                        const float* __restrict__ w1, const float* __restrict__ b1,
                        const float* __restrict__ b2) {
    __shared__ float su[DIM];
    __shared__ float2 sea[16];
    __shared__ int sdst[16];
    __shared__ ull sh2[HID][10];    // [k][pair0..7], row 80B (16B-aligned)  10KB
    __shared__ ull red[32][33];     // [p*4+kq][o]                           8.4KB
    int s = blockIdx.x;
    int lo = g_rowptr[s], hi = g_rowptr[s + 1];
    if (lo >= hi) return;
    int t = threadIdx.x;
    int kq = t >> 5, o = t & 31;

    float w1c0 = __ldg(&w1[t]), w1c1 = __ldg(&w1[HID + t]), b1c = __ldg(&b1[t]);
    if (t < DIM) su[t] = g_out[s * DIM + t];
    __syncthreads();

    float ub = 0.f;
#pragma unroll
    for (int d = 0; d < DIM; d++) ub += su[d] * __ldg(&b2[d * DIM + o]);

    ull vp[32];
    const float* Vs = g_V + (size_t)s * KDIM + kq * 32 * 32 + o;
#pragma unroll
    for (int kk = 0; kk < 32; kk++) {
        float v = Vs[kk * 32];
        vp[kk] = pk2(v, v);
    }

    for (int base = lo; base < hi; base += 16) {
        int m = hi - base; if (m > 16) m = 16;
        __syncthreads();   // prior batch fully consumed (red read, sdst used)
        if (t < m) {
            int e = g_eids[base + t];
            sea[t] = *(const float2*)&ea[2 * e];
            sdst[t] = ei[EE + e];
        }
        __syncthreads();
        // edge-MLP hidden for my k=t, all 8 pairs; zero-fill beyond m
        ull hp[8];
#pragma unroll
        for (int p = 0; p < 8; p++) {
            float h0 = 0.f, h1 = 0.f;
            if (2 * p < m) {
                float v = sea[2 * p].x * w1c0 + sea[2 * p].y * w1c1 + b1c;
                h0 = v > 0.f ? v : 0.f;
            }
            if (2 * p + 1 < m) {
                float v = sea[2 * p + 1].x * w1c0 + sea[2 * p + 1].y * w1c1 + b1c;
                h1 = v > 0.f ? v : 0.f;
            }
            hp[p] = pk2(h0, h1);
        }
        *(ulonglong2*)&sh2[t][0] = make_ulonglong2(hp[0], hp[1]);
        *(ulonglong2*)&sh2[t][2] = make_ulonglong2(hp[2], hp[3]);
        *(ulonglong2*)&sh2[t][4] = make_ulonglong2(hp[4], hp[5]);
        *(ulonglong2*)&sh2[t][6] = make_ulonglong2(hp[6], hp[7]);
        __syncthreads();

        ull acc[8];
#pragma unroll
        for (int p = 0; p < 8; p++) acc[p] = 0ull;
#pragma unroll 4
        for (int kk = 0; kk < 32; kk++) {
            const ull* hrow = sh2[kq * 32 + kk];
            ulonglong2 h01 = *(const ulonglong2*)&hrow[0];
            ulonglong2 h23 = *(const ulonglong2*)&hrow[2];
            ulonglong2 h45 = *(const ulonglong2*)&hrow[4];
            ulonglong2 h67 = *(const ulonglong2*)&hrow[6];
            ull v = vp[kk];
            acc[0] = ffma2(h01.x, v, acc[0]);
            acc[1] = ffma2(h01.y, v, acc[1]);
            acc[2] = ffma2(h23.x, v, acc[2]);
            acc[3] = ffma2(h23.y, v, acc[3]);
            acc[4] = ffma2(h45.x, v, acc[4]);
            acc[5] = ffma2(h45.y, v, acc[5]);
            acc[6] = ffma2(h67.x, v, acc[6]);
            acc[7] = ffma2(h67.y, v, acc[7]);
        }
#pragma unroll
        for (int p = 0; p < 8; p++) red[p * 4 + kq][o] = acc[p];
        __syncthreads();
        // finalize: thread (kq,o) sums + scatters pairs kq and kq+4
#pragma unroll
        for (int r = 0; r < 2; r++) {
            int p = kq + 4 * r;
            ull sum = add2(add2(red[p * 4 + 0][o], red[p * 4 + 1][o]),
                           add2(red[p * 4 + 2][o], red[p * 4 + 3][o]));
            float2 ms = upk2(sum);
            if (2 * p < m)     atomicAdd(&g_agg[sdst[2 * p] * DIM + o], ms.x + ub);
            if (2 * p + 1 < m) atomicAdd(&g_agg[sdst[2 * p + 1] * DIM + o], ms.y + ub);
        }
    }
}

// ---------------- node update: mean + root + GRU (re-zeroes g_agg) ----------------
__global__ void k_update(const float* __restrict__ rootw,
                         const float* __restrict__ convb,
                         const float* __restrict__ wih,
                         const float* __restrict__ whh,
                         const float* __restrict__ bih,
                         const float* __restrict__ bhh) {
    __shared__ float Msm[8][DIM];
    int n = blockIdx.x * 8 + (threadIdx.x >> 5);
    int o = threadIdx.x & 31;
    int nl = threadIdx.x >> 5;

    float aggv = g_agg[n * DIM + o];
    g_agg[n * DIM + o] = 0.f;
    float agg = aggv / g_deg[n];
    float mo = agg + __ldg(&convb[o]);
#pragma unroll
    for (int d = 0; d < DIM; d++) mo += g_out[n * DIM + d] * __ldg(&rootw[d * DIM + o]);
    mo = mo > 0.f ? mo : 0.f;
    Msm[nl][o] = mo;
    __syncthreads();

    float ir = __ldg(&bih[o]), iz = __ldg(&bih[32 + o]), inn = __ldg(&bih[64 + o]);
    float hr = __ldg(&bhh[o]), hz = __ldg(&bhh[32 + o]), hn = __ldg(&bhh[64 + o]);
#pragma unroll
    for (int d = 0; d < DIM; d++) {
        float md = Msm[nl][d];
        float hd = g_out[n * DIM + d];
        ir += md * __ldg(&wih[d * 96 + o]);
        iz += md * __ldg(&wih[d * 96 + 32 + o]);
        inn += md * __ldg(&wih[d * 96 + 64 + o]);
        hr += hd * __ldg(&whh[d * 96 + o]);
        hz += hd * __ldg(&whh[d * 96 + 32 + o]);
        hn += hd * __ldg(&whh[d * 96 + 64 + o]);
    }
    float r = sigm(ir + hr);
    float z = sigm(iz + hz);
    float nv = tanhf(inn + r * hn);
    float hold = g_out[n * DIM + o];
    float hnew = (1.f - z) * nv + z * hold;
    __syncwarp();
    g_out[n * DIM + o] = hnew;
}

// ---------------- Set2Set: fused LSTM + attention (+ final MLP on last step) ----------------
__global__ void k_s2s(int step, int last,
                      const float* __restrict__ wih, const float* __restrict__ whh,
                      const float* __restrict__ bih, const float* __restrict__ bhh,
                      const float* __restrict__ l1w, const float* __restrict__ l1b,
                      const float* __restrict__ l2w, const float* __restrict__ l2b,
                      float* __restrict__ yout) {
    __shared__ float gs[128];
    __shared__ float sqh[32];
    __shared__ float rfin[32];
    __shared__ float ebuf[4096];
    __shared__ float wred[8];
    __shared__ float rpart[8][32];
    __shared__ float s_bmax, s_den;
    int b = blockIdx.x;
    int tid = threadIdx.x;
    int w = tid >> 5, lane = tid & 31;

    if (tid < 128) {
        float g = __ldg(&bih[tid]) + __ldg(&bhh[tid]);
        if (step > 0) {
#pragma unroll
            for (int t = 0; t < 2 * DIM; t++)
                g += g_qstar[b * 2 * DIM + t] * __ldg(&wih[t * 128 + tid]);
#pragma unroll
            for (int t = 0; t < DIM; t++)
                g += g_qh[b * DIM + t] * __ldg(&whh[t * 128 + tid]);
        }
        gs[tid] = g;
    }
    __syncthreads();
    if (tid < 32) {
        float qc_old = (step > 0) ? g_qc[b * DIM + tid] : 0.f;
        float qc = sigm(gs[32 + tid]) * qc_old + sigm(gs[tid]) * tanhf(gs[64 + tid]);
        g_qc[b * DIM + tid] = qc;
        float qh = sigm(gs[96 + tid]) * tanhf(qc);
        g_qh[b * DIM + tid] = qh;
        sqh[tid] = qh;
    }
    __syncthreads();

    int lo = g_gptr[b], hi = g_gptr[b + 1];
    int cnt = hi - lo;

    float mymax = -1e30f;
    for (int i = lo + w; i < hi; i += 8) {
        float v = g_out[(size_t)i * DIM + lane] * sqh[lane];
#pragma unroll
        for (int off = 16; off; off >>= 1) v += __shfl_xor_sync(0xffffffffu, v, off);
        if (lane == 0) ebuf[i - lo] = v;
        mymax = fmaxf(mymax, v);
    }
    if (lane == 0) wred[w] = mymax;
    __syncthreads();
    if (tid == 0) {
        float m = -1e30f;
        for (int q = 0; q < 8; q++) m = fmaxf(m, wred[q]);
        s_bmax = m;
    }
    __syncthreads();
    float bm = s_bmax;

    float ssum = 0.f;
    for (int idx = tid; idx < cnt; idx += 256) {
        float ev = expf(ebuf[idx] - bm);
        ebuf[idx] = ev;
        ssum += ev;
    }
#pragma unroll
    for (int off = 16; off; off >>= 1) ssum += __shfl_xor_sync(0xffffffffu, ssum, off);
    if (lane == 0) wred[w] = ssum;
    __syncthreads();
    if (tid == 0) {
        float tt = 0.f;
        for (int q = 0; q < 8; q++) tt += wred[q];
        s_den = tt;
    }
    __syncthreads();
    float invden = (cnt > 0 && s_den > 0.f) ? 1.f / s_den : 0.f;

    float rl = 0.f;
    for (int i = lo + w; i < hi; i += 8) {
        float a = ebuf[i - lo] * invden;
        rl += a * g_out[(size_t)i * DIM + lane];
    }
    rpart[w][lane] = rl;
    __syncthreads();
    if (w == 0) {
        float r = 0.f;
#pragma unroll
        for (int q = 0; q < 8; q++) r += rpart[q][lane];
        rfin[lane] = r;
        g_qstar[b * 2 * DIM + 32 + lane] = r;
        g_qstar[b * 2 * DIM + lane] = sqh[lane];
    }

    if (last) {
        __syncthreads();
        if (tid < 32) {
            int j = tid;
            float hj = __ldg(&l1b[j]);
#pragma unroll
            for (int t = 0; t < DIM; t++) hj += sqh[t] * __ldg(&l1w[t * DIM + j]);
#pragma unroll
            for (int t = 0; t < DIM; t++) hj += rfin[t] * __ldg(&l1w[(DIM + t) * DIM + j]);
            hj = hj > 0.f ? hj : 0.f;
            float v = hj * __ldg(&l2w[j]);
#pragma unroll
            for (int off = 16; off; off >>= 1) v += __shfl_xor_sync(0xffffffffu, v, off);
            if (j == 0) yout[b] = v + __ldg(&l2b[0]);
        }
    }
}

// ---------------- launch ----------------
extern "C" void kernel_launch(void* const* d_in, const int* in_sizes, int n_in,
                              void* d_out, int out_size) {
    const float* x       = (const float*)d_in[0];
    const float* ea      = (const float*)d_in[1];
    const float* lin0w   = (const float*)d_in[2];
    const float* lin0b   = (const float*)d_in[3];
    const float* ennw1   = (const float*)d_in[4];
    const float* ennb1   = (const float*)d_in[5];
    const float* ennw2   = (const float*)d_in[6];
    const float* ennb2   = (const float*)d_in[7];
    const float* rootw   = (const float*)d_in[8];
    const float* convb   = (const float*)d_in[9];
    const float* gruwih  = (const float*)d_in[10];
    const float* gruwhh  = (const float*)d_in[11];
    const float* grubih  = (const float*)d_in[12];
    const float* grubhh  = (const float*)d_in[13];
    const float* s2swih  = (const float*)d_in[14];
    const float* s2swhh  = (const float*)d_in[15];
    const float* s2sbih  = (const float*)d_in[16];
    const float* s2sbhh  = (const float*)d_in[17];
    const float* lin1w   = (const float*)d_in[18];
    const float* lin1b   = (const float*)d_in[19];
    const float* lin2w   = (const float*)d_in[20];
    const float* lin2b   = (const float*)d_in[21];
    const int*   ei      = (const int*)d_in[22];
    const int*   batch   = (const int*)d_in[23];
    float* yout = (float*)d_out;

    k_zeroinit<<<(NN * DIM + 1023) / 1024, 1024>>>(x, lin0w, lin0b);
    k_count<<<(EE + 255) / 256, 256>>>(ei);
    k_scan<<<1, 1024>>>();
    k_fill<<<(EE + 255) / 256, 256>>>(ei, batch);

    for (int it = 0; it < NMP; it++) {
        k_vgemm<<<2048, 256>>>(ennw2);
        k_edges<<<NN, 128>>>(ei, ea, ennw1, ennb1, ennb2);
        k_update<<<NN / 8, 256>>>(rootw, convb, gruwih, gruwhh, grubih, grubhh);
    }

    for (int s = 0; s < S2S; s++) {
        k_s2s<<<BG, 256>>>(s, s == S2S - 1 ? 1 : 0,
                           s2swih, s2swhh, s2sbih, s2sbhh,
                           lin1w, lin1b, lin2w, lin2b, yout);
    }
}

// round 11
// speedup vs baseline: 1.3012x; 1.3012x over previous
#include <cuda_runtime.h>
#include <math.h>

#define NN 8192
#define EE 131072
#define DIM 32
#define HID 128
#define BG 64
#define NMP 3
#define S2S 3
#define KDIM 4096   // HID*DIM

typedef unsigned long long ull;

__device__ __forceinline__ ull pk2(float lo, float hi) {
    ull r; asm("mov.b64 %0,{%1,%2};" : "=l"(r) : "f"(lo), "f"(hi)); return r;
}
__device__ __forceinline__ float2 upk2(ull v) {
    float2 r; asm("mov.b64 {%0,%1},%2;" : "=f"(r.x), "=f"(r.y) : "l"(v)); return r;
}
__device__ __forceinline__ ull ffma2(ull a, ull b, ull c) {
    ull d; asm("fma.rn.f32x2 %0,%1,%2,%3;" : "=l"(d) : "l"(a), "l"(b), "l"(c)); return d;
}
__device__ __forceinline__ ull add2(ull a, ull b) {
    ull d; asm("add.rn.f32x2 %0,%1,%2;" : "=l"(d) : "l"(a), "l"(b)); return d;
}

// ---------------- scratch (device globals; no allocation) ----------------
__device__ float g_out[NN * DIM];            // node features / GRU hidden
__device__ float g_V[(size_t)NN * KDIM];     // V[s][k][o]
__device__ float g_agg[NN * DIM];            // atomic message accum (re-zeroed by k_update)
__device__ int   g_cnt[NN];
__device__ int   g_dcnt[NN];
__device__ int   g_rowptr[NN + 1];
__device__ int   g_woff[NN];
__device__ int   g_eids[EE];
__device__ float g_deg[NN];
__device__ int   g_gptr[BG + 1];
__device__ float g_qh[BG * DIM];
__device__ float g_qc[BG * DIM];
__device__ float g_qstar[BG * 2 * DIM];

__device__ __forceinline__ float sigm(float x) { return 1.0f / (1.0f + expf(-x)); }

// ---------------- setup ----------------
__global__ void k_zeroinit(const float* __restrict__ x,
                           const float* __restrict__ w0,
                           const float* __restrict__ b0) {
    int idx = blockIdx.x * blockDim.x + threadIdx.x;
    if (idx < NN) { g_cnt[idx] = 0; g_dcnt[idx] = 0; }
    if (idx < NN * DIM) {
        int n = idx >> 5, j = idx & 31;
        float v = x[n] * w0[j] + b0[j];
        g_out[idx] = v > 0.f ? v : 0.f;
    }
}

// 1 edge/thread, 512 blocks: max warps in flight to hide atomic latency
__global__ void k_count(const int* __restrict__ ei) {
    int e = blockIdx.x * blockDim.x + threadIdx.x;
    if (e < EE) {
        atomicAdd(&g_cnt[ei[e]], 1);          // src (CSR grouping)
        atomicAdd(&g_dcnt[ei[EE + e]], 1);    // dst (degree for mean)
    }
}

// shfl-based exclusive scan of src counts -> rowptr/woff; deg from dcnt
__global__ void k_scan() {
    __shared__ int wsum[32], wscan[32];
    int t = threadIdx.x, lane = t & 31, wid = t >> 5;
    int base = t * 8;
    int v[8]; int csum = 0;
#pragma unroll
    for (int i = 0; i < 8; i++) { v[i] = g_cnt[base + i]; csum += v[i]; }
    int inc = csum;
#pragma unroll
    for (int off = 1; off < 32; off <<= 1) {
        int nv = __shfl_up_sync(0xffffffffu, inc, off);
        if (lane >= off) inc += nv;
    }
    if (lane == 31) wsum[wid] = inc;
    __syncthreads();
    if (t < 32) {
        int w = wsum[t];
#pragma unroll
        for (int off = 1; off < 32; off <<= 1) {
            int nv = __shfl_up_sync(0xffffffffu, w, off);
            if (t >= off) w += nv;
        }
        wscan[t] = w;
    }
    __syncthreads();
    int run = inc - csum + (wid > 0 ? wscan[wid - 1] : 0);
#pragma unroll
    for (int i = 0; i < 8; i++) {
        g_rowptr[base + i] = run;
        g_woff[base + i] = run;
        run += v[i];
    }
    if (t == 1023) g_rowptr[NN] = run;
#pragma unroll
    for (int i = 0; i < 8; i++) {
        int d = g_dcnt[base + i];
        g_deg[base + i] = (float)(d > 0 ? d : 1);
    }
}

// CSR fill, 1 edge/thread (+ per-graph ranges in block 0)
__global__ void k_fill(const int* __restrict__ ei, const int* __restrict__ batch) {
    int e = blockIdx.x * blockDim.x + threadIdx.x;
    if (e < EE) {
        int src = ei[e];
        int pos = atomicAdd(&g_woff[src], 1);
        g_eids[pos] = e;
    }
    if (blockIdx.x == 0 && threadIdx.x <= BG) {
        int b = threadIdx.x;
        int lo = 0, hi = NN;
        while (lo < hi) {
            int mid = (lo + hi) >> 1;
            if (batch[mid] < b) lo = mid + 1; else hi = mid;
        }
        g_gptr[b] = lo;
    }
}

// ---------------- V GEMM: V[N,4096] = out[N,32] @ B[32,4096] ----------------
// grid 2048 = 128 node-tiles x 16 r-chunks (256 cols each); block 256.
__global__ void k_vgemm(const float* __restrict__ w2) {
    __shared__ ull  At2[64][32];    // [n][d] pk2(a,a)   16KB
    __shared__ float Bs[32][256];   // [d][rr]           32KB
    int tid = threadIdx.x;
    int ntile = blockIdx.x & 127;
    int rchunk = blockIdx.x >> 7;
    int rbase = rchunk * 256;
    int nodebase = ntile * 64;

#pragma unroll
    for (int i = 0; i < 8; i++) {
        int s = i * 256 + tid;
        int n = s >> 5, d = s & 31;
        float a = g_out[(nodebase + n) * DIM + d];
        At2[n][d] = pk2(a, a);
    }
#pragma unroll
    for (int i = 0; i < 8; i++) {
        int s = i * 256 + tid;
        int d = s >> 6, rq = s & 63;
        int r = rbase + rq * 4;
        int k = r >> 5, o = r & 31;
        *(float4*)&Bs[d][rq * 4] = *(const float4*)&w2[(size_t)k * 1024 + d * 32 + o];
    }
    __syncthreads();

    int w = tid >> 5, l = tid & 31;
    ull acc[8][4];
#pragma unroll
    for (int j = 0; j < 8; j++)
#pragma unroll
        for (int q = 0; q < 4; q++) acc[j][q] = 0ull;

#pragma unroll 4
    for (int d = 0; d < 32; d++) {
        ull b0 = *(const ull*)&Bs[d][2 * l];
        ull b1 = *(const ull*)&Bs[d][64 + 2 * l];
        ull b2 = *(const ull*)&Bs[d][128 + 2 * l];
        ull b3 = *(const ull*)&Bs[d][192 + 2 * l];
#pragma unroll
        for (int j = 0; j < 8; j++) {
            ull a = At2[w + 8 * j][d];
            acc[j][0] = ffma2(a, b0, acc[j][0]);
            acc[j][1] = ffma2(a, b1, acc[j][1]);
            acc[j][2] = ffma2(a, b2, acc[j][2]);
            acc[j][3] = ffma2(a, b3, acc[j][3]);
        }
    }
#pragma unroll
    for (int j = 0; j < 8; j++) {
        int n = nodebase + w + 8 * j;
        float* Vr = g_V + (size_t)n * KDIM + rbase;
#pragma unroll
        for (int q = 0; q < 4; q++) {
            float2 v = upk2(acc[j][q]);
            *(float2*)&Vr[64 * q + 2 * l] = v;
        }
    }
}

// ---------------- edge contraction + scatter (per src node) ----------------
// R9 structure (8-edge batches, sh[p][k] staging) with two local changes:
//  - inner h reads vectorized to LDS.128 (two packs per load, two acc chains)
//  - pairs beyond m skipped entirely in remainder batches
__global__ void k_edges(const int* __restrict__ ei, const float* __restrict__ ea,
                        const float* __restrict__ w1, const float* __restrict__ b1,
                        const float* __restrict__ b2) {
    __shared__ float su[DIM];
    __shared__ float2 sea[8];
    __shared__ int sdst[8];
    __shared__ ull sh[4][HID];
    __shared__ ull red[16 * 33];
    int s = blockIdx.x;
    int lo = g_rowptr[s], hi = g_rowptr[s + 1];
    if (lo >= hi) return;
    int t = threadIdx.x;
    int kq = t >> 5, o = t & 31;

    float w1c0 = __ldg(&w1[t]), w1c1 = __ldg(&w1[HID + t]), b1c = __ldg(&b1[t]);
    if (t < DIM) su[t] = g_out[s * DIM + t];
    __syncthreads();

    float ub = 0.f;
#pragma unroll
    for (int d = 0; d < DIM; d++) ub += su[d] * __ldg(&b2[d * DIM + o]);

    ull vp[32];
    const float* Vs = g_V + (size_t)s * KDIM + kq * 32 * 32 + o;
#pragma unroll
    for (int kk = 0; kk < 32; kk++) {
        float v = Vs[kk * 32];
        vp[kk] = pk2(v, v);
    }

    for (int base = lo; base < hi; base += 8) {
        int m = hi - base; if (m > 8) m = 8;
        __syncthreads();
        if (t < m) {
            int e = g_eids[base + t];
            sea[t] = *(const float2*)&ea[2 * e];
            sdst[t] = ei[EE + e];
        }
        __syncthreads();
#pragma unroll
        for (int p = 0; p < 4; p++) {
            float h0 = 0.f, h1 = 0.f;
            if (2 * p < m) {
                float v = sea[2 * p].x * w1c0 + sea[2 * p].y * w1c1 + b1c;
                h0 = v > 0.f ? v : 0.f;
            }
            if (2 * p + 1 < m) {
                float v = sea[2 * p + 1].x * w1c0 + sea[2 * p + 1].y * w1c1 + b1c;
                h1 = v > 0.f ? v : 0.f;
            }
            sh[p][t] = pk2(h0, h1);
        }
        __syncthreads();
#pragma unroll
        for (int p = 0; p < 4; p++) {
            if (2 * p < m) {
                ull acc0 = 0, acc1 = 0;
                const ulonglong2* shp = (const ulonglong2*)&sh[p][kq * 32];
#pragma unroll
                for (int kk = 0; kk < 16; kk++) {
                    ulonglong2 hh = shp[kk];
                    acc0 = ffma2(hh.x, vp[2 * kk], acc0);
                    acc1 = ffma2(hh.y, vp[2 * kk + 1], acc1);
                }
                red[(p * 4 + kq) * 33 + o] = add2(acc0, acc1);
            }
        }
        __syncthreads();
        {
            int p = kq;
            if (2 * p < m) {
                ull sum = add2(add2(red[(p * 4 + 0) * 33 + o], red[(p * 4 + 1) * 33 + o]),
                               add2(red[(p * 4 + 2) * 33 + o], red[(p * 4 + 3) * 33 + o]));
                float2 ms = upk2(sum);
                atomicAdd(&g_agg[sdst[2 * p] * DIM + o], ms.x + ub);
                if (2 * p + 1 < m) atomicAdd(&g_agg[sdst[2 * p + 1] * DIM + o], ms.y + ub);
            }
        }
    }
}

// ---------------- node update: mean + root + GRU (re-zeroes g_agg) ----------------
__global__ void k_update(const float* __restrict__ rootw,
                         const float* __restrict__ convb,
                         const float* __restrict__ wih,
                         const float* __restrict__ whh,
                         const float* __restrict__ bih,
                         const float* __restrict__ bhh) {
    __shared__ float Msm[8][DIM];
    int n = blockIdx.x * 8 + (threadIdx.x >> 5);
    int o = threadIdx.x & 31;
    int nl = threadIdx.x >> 5;

    float aggv = g_agg[n * DIM + o];
    g_agg[n * DIM + o] = 0.f;
    float agg = aggv / g_deg[n];
    float mo = agg + __ldg(&convb[o]);
#pragma unroll
    for (int d = 0; d < DIM; d++) mo += g_out[n * DIM + d] * __ldg(&rootw[d * DIM + o]);
    mo = mo > 0.f ? mo : 0.f;
    Msm[nl][o] = mo;
    __syncthreads();

    float ir = __ldg(&bih[o]), iz = __ldg(&bih[32 + o]), inn = __ldg(&bih[64 + o]);
    float hr = __ldg(&bhh[o]), hz = __ldg(&bhh[32 + o]), hn = __ldg(&bhh[64 + o]);
#pragma unroll
    for (int d = 0; d < DIM; d++) {
        float md = Msm[nl][d];
        float hd = g_out[n * DIM + d];
        ir += md * __ldg(&wih[d * 96 + o]);
        iz += md * __ldg(&wih[d * 96 + 32 + o]);
        inn += md * __ldg(&wih[d * 96 + 64 + o]);
        hr += hd * __ldg(&whh[d * 96 + o]);
        hz += hd * __ldg(&whh[d * 96 + 32 + o]);
        hn += hd * __ldg(&whh[d * 96 + 64 + o]);
    }
    float r = sigm(ir + hr);
    float z = sigm(iz + hz);
    float nv = tanhf(inn + r * hn);
    float hold = g_out[n * DIM + o];
    float hnew = (1.f - z) * nv + z * hold;
    __syncwarp();
    g_out[n * DIM + o] = hnew;
}

// ---------------- Set2Set: fused LSTM + attention (+ final MLP on last step) ----------------
__global__ void k_s2s(int step, int last,
                      const float* __restrict__ wih, const float* __restrict__ whh,
                      const float* __restrict__ bih, const float* __restrict__ bhh,
                      const float* __restrict__ l1w, const float* __restrict__ l1b,
                      const float* __restrict__ l2w, const float* __restrict__ l2b,
                      float* __restrict__ yout) {
    __shared__ float gs[128];
    __shared__ float sqh[32];
    __shared__ float rfin[32];
    __shared__ float ebuf[4096];
    __shared__ float wred[8];
    __shared__ float rpart[8][32];
    __shared__ float s_bmax, s_den;
    int b = blockIdx.x;
    int tid = threadIdx.x;
    int w = tid >> 5, lane = tid & 31;

    if (tid < 128) {
        float g = __ldg(&bih[tid]) + __ldg(&bhh[tid]);
        if (step > 0) {
#pragma unroll
            for (int t = 0; t < 2 * DIM; t++)
                g += g_qstar[b * 2 * DIM + t] * __ldg(&wih[t * 128 + tid]);
#pragma unroll
            for (int t = 0; t < DIM; t++)
                g += g_qh[b * DIM + t] * __ldg(&whh[t * 128 + tid]);
        }
        gs[tid] = g;
    }
    __syncthreads();
    if (tid < 32) {
        float qc_old = (step > 0) ? g_qc[b * DIM + tid] : 0.f;
        float qc = sigm(gs[32 + tid]) * qc_old + sigm(gs[tid]) * tanhf(gs[64 + tid]);
        g_qc[b * DIM + tid] = qc;
        float qh = sigm(gs[96 + tid]) * tanhf(qc);
        g_qh[b * DIM + tid] = qh;
        sqh[tid] = qh;
    }
    __syncthreads();

    int lo = g_gptr[b], hi = g_gptr[b + 1];
    int cnt = hi - lo;

    float mymax = -1e30f;
    for (int i = lo + w; i < hi; i += 8) {
        float v = g_out[(size_t)i * DIM + lane] * sqh[lane];
#pragma unroll
        for (int off = 16; off; off >>= 1) v += __shfl_xor_sync(0xffffffffu, v, off);
        if (lane == 0) ebuf[i - lo] = v;
        mymax = fmaxf(mymax, v);
    }
    if (lane == 0) wred[w] = mymax;
    __syncthreads();
    if (tid == 0) {
        float m = -1e30f;
        for (int q = 0; q < 8; q++) m = fmaxf(m, wred[q]);
        s_bmax = m;
    }
    __syncthreads();
    float bm = s_bmax;

    float ssum = 0.f;
    for (int idx = tid; idx < cnt; idx += 256) {
        float ev = expf(ebuf[idx] - bm);
        ebuf[idx] = ev;
        ssum += ev;
    }
#pragma unroll
    for (int off = 16; off; off >>= 1) ssum += __shfl_xor_sync(0xffffffffu, ssum, off);
    if (lane == 0) wred[w] = ssum;
    __syncthreads();
    if (tid == 0) {
        float tt = 0.f;
        for (int q = 0; q < 8; q++) tt += wred[q];
        s_den = tt;
    }
    __syncthreads();
    float invden = (cnt > 0 && s_den > 0.f) ? 1.f / s_den : 0.f;

    float rl = 0.f;
    for (int i = lo + w; i < hi; i += 8) {
        float a = ebuf[i - lo] * invden;
        rl += a * g_out[(size_t)i * DIM + lane];
    }
    rpart[w][lane] = rl;
    __syncthreads();
    if (w == 0) {
        float r = 0.f;
#pragma unroll
        for (int q = 0; q < 8; q++) r += rpart[q][lane];
        rfin[lane] = r;
        g_qstar[b * 2 * DIM + 32 + lane] = r;
        g_qstar[b * 2 * DIM + lane] = sqh[lane];
    }

    if (last) {
        __syncthreads();
        if (tid < 32) {
            int j = tid;
            float hj = __ldg(&l1b[j]);
#pragma unroll
            for (int t = 0; t < DIM; t++) hj += sqh[t] * __ldg(&l1w[t * DIM + j]);
#pragma unroll
            for (int t = 0; t < DIM; t++) hj += rfin[t] * __ldg(&l1w[(DIM + t) * DIM + j]);
            hj = hj > 0.f ? hj : 0.f;
            float v = hj * __ldg(&l2w[j]);
#pragma unroll
            for (int off = 16; off; off >>= 1) v += __shfl_xor_sync(0xffffffffu, v, off);
            if (j == 0) yout[b] = v + __ldg(&l2b[0]);
        }
    }
}

// ---------------- launch ----------------
extern "C" void kernel_launch(void* const* d_in, const int* in_sizes, int n_in,
                              void* d_out, int out_size) {
    const float* x       = (const float*)d_in[0];
    const float* ea      = (const float*)d_in[1];
    const float* lin0w   = (const float*)d_in[2];
    const float* lin0b   = (const float*)d_in[3];
    const float* ennw1   = (const float*)d_in[4];
    const float* ennb1   = (const float*)d_in[5];
    const float* ennw2   = (const float*)d_in[6];
    const float* ennb2   = (const float*)d_in[7];
    const float* rootw   = (const float*)d_in[8];
    const float* convb   = (const float*)d_in[9];
    const float* gruwih  = (const float*)d_in[10];
    const float* gruwhh  = (const float*)d_in[11];
    const float* grubih  = (const float*)d_in[12];
    const float* grubhh  = (const float*)d_in[13];
    const float* s2swih  = (const float*)d_in[14];
    const float* s2swhh  = (const float*)d_in[15];
    const float* s2sbih  = (const float*)d_in[16];
    const float* s2sbhh  = (const float*)d_in[17];
    const float* lin1w   = (const float*)d_in[18];
    const float* lin1b   = (const float*)d_in[19];
    const float* lin2w   = (const float*)d_in[20];
    const float* lin2b   = (const float*)d_in[21];
    const int*   ei      = (const int*)d_in[22];
    const int*   batch   = (const int*)d_in[23];
    float* yout = (float*)d_out;

    k_zeroinit<<<(NN * DIM + 1023) / 1024, 1024>>>(x, lin0w, lin0b);
    k_count<<<(EE + 255) / 256, 256>>>(ei);
    k_scan<<<1, 1024>>>();
    k_fill<<<(EE + 255) / 256, 256>>>(ei, batch);

    for (int it = 0; it < NMP; it++) {
        k_vgemm<<<2048, 256>>>(ennw2);
        k_edges<<<NN, 128>>>(ei, ea, ennw1, ennb1, ennb2);
        k_update<<<NN / 8, 256>>>(rootw, convb, gruwih, gruwhh, grubih, grubhh);
    }

    for (int s = 0; s < S2S; s++) {
        k_s2s<<<BG, 256>>>(s, s == S2S - 1 ? 1 : 0,
                           s2swih, s2swhh, s2sbih, s2sbhh,
                           lin1w, lin1b, lin2w, lin2b, yout);
    }
}